// round 10
// baseline (speedup 1.0000x reference)
#include <cuda_runtime.h>
#include <cstdint>

#define BATCH   1024
#define WDIM    256
#define HDIM    256
#define DEPTH   8
#define HMAX    256     // absolute worst-case hull size
#define HP      16      // padded fast-path hull size (Gaussian data: ~6-10 lines)

#define F_INF   __int_as_float(0x7F800000)
#define F_NINF  __int_as_float(0xFF800000)

// Static device scratch (allocation-free rule).
// Padded hulls: per (branch,d,w) 8 granules of 16B; granule g holds lines
// 2g,2g+1 as (m0, m1, b0, b1) so an LDS.128 yields (m0,m1),(b0,b1) b64 pairs.
__device__ float2 g_hull [2][DEPTH][WDIM][HMAX];  // oversized tail (k >= HP only)
__device__ float4 g_hullp[2][DEPTH][WDIM][HP/2];  // 8 granules = 128B per w
__device__ int    g_cnt  [2][DEPTH][WDIM];

// Monotone float <-> uint key (uint order == float order, incl. +-inf).
__device__ __forceinline__ unsigned fkey(float f) {
    unsigned u = __float_as_uint(f);
    return (u & 0x80000000u) ? ~u : (u | 0x80000000u);
}
__device__ __forceinline__ float funkey(unsigned k) {
    unsigned u = (k & 0x80000000u) ? (k & 0x7FFFFFFFu) : ~k;
    return __uint_as_float(u);
}

#define CP_ASYNC16(dst, src) \
    asm volatile("cp.async.cg.shared.global [%0], [%1], 16;" :: "r"(dst), "l"(src))
#define CP_COMMIT() asm volatile("cp.async.commit_group;")
#define CP_WAIT(n)  asm volatile("cp.async.wait_group %0;" :: "n"(n))

// Packed f32x2 helpers (FFMA2 in SASS; movs collapse to register-pair naming).
__device__ __forceinline__ uint64_t pack_dup(float f) {
    uint64_t r;
    asm("mov.b64 %0, {%1, %1};" : "=l"(r) : "f"(f));
    return r;
}
__device__ __forceinline__ void ffma2(uint64_t& d, uint64_t a, uint64_t b, uint64_t c) {
    asm("fma.rn.f32x2 %0, %1, %2, %3;" : "=l"(d) : "l"(a), "l"(b), "l"(c));
}
__device__ __forceinline__ void unpack2(float& lo, float& hi, uint64_t v) {
    asm("mov.b64 {%0, %1}, %2;" : "=f"(lo), "=f"(hi) : "l"(v));
}

// Write line k of a padded hull in granule layout (m0,m1,b0,b1).
__device__ __forceinline__ void store_line(float* hps, int k, float m, float b) {
    int g = k >> 1, o = k & 1;
    hps[g * 4 + o]     = m;
    hps[g * 4 + 2 + o] = b;
}

// ───────────────────────── hull kernel ─────────────────────────
// One warp per envelope (branch, d, w): gift-wrap the upper envelope of the
// 256 lines y = m*q + b. 8 independent fdividefs per lane-step, REDUX argmin.
__global__ void __launch_bounds__(256) hull_kernel(
    const float* __restrict__ M1, const float* __restrict__ B1,
    const float* __restrict__ M2, const float* __restrict__ B2) {
    const int gw     = (blockIdx.x * blockDim.x + threadIdx.x) >> 5;  // 0..4095
    const int lane   = threadIdx.x & 31;
    const int branch = gw >> 11;
    const int d      = (gw >> 8) & 7;
    const int w      = gw & 255;

    const float* Mp = (branch ? M2 : M1) + (size_t)((d << 8) + w) * HDIM;
    const float* Bp = (branch ? B2 : B1) + (size_t)((d << 8) + w) * HDIM;

    float m[8], b[8];
    {
        const float4* M4 = (const float4*)Mp;
        const float4* B4 = (const float4*)Bp;
        float4 a0 = M4[lane * 2], a1 = M4[lane * 2 + 1];
        float4 c0 = B4[lane * 2], c1 = B4[lane * 2 + 1];
        m[0]=a0.x; m[1]=a0.y; m[2]=a0.z; m[3]=a0.w;
        m[4]=a1.x; m[5]=a1.y; m[6]=a1.z; m[7]=a1.w;
        b[0]=c0.x; b[1]=c0.y; b[2]=c0.z; b[3]=c0.w;
        b[4]=c1.x; b[5]=c1.y; b[6]=c1.z; b[7]=c1.w;
    }

    // Start line: min slope (dominated equal-slope start self-corrects).
    float mc = m[0], bc = b[0];
#pragma unroll
    for (int k = 1; k < 8; k++)
        if (m[k] < mc || (m[k] == mc && b[k] > bc)) { mc = m[k]; bc = b[k]; }
    {
        unsigned mk  = __reduce_min_sync(0xFFFFFFFFu, fkey(mc));
        unsigned bal = __ballot_sync(0xFFFFFFFFu, fkey(mc) == mk);
        int src = __ffs(bal) - 1;
        mc = __shfl_sync(0xFFFFFFFFu, mc, src);
        bc = __shfl_sync(0xFFFFFFFFu, bc, src);
    }

    float2* hf  = &g_hull[branch][d][w][0];
    float*  hps = (float*)&g_hullp[branch][d][w][0];
    const unsigned KEY_INF = fkey(F_INF);

    int cnt = 0;
    for (int step = 0; step < HMAX; ++step) {
        if (lane == 0) {
            if (cnt < HP) store_line(hps, cnt, mc, bc);
            else          hf[cnt] = make_float2(mc, bc);
        }
        cnt++;

        // Per-lane: smallest crossing x among overtaking lines.
        // dj==0 && nj<0 encodes x = -inf via fdividef (-/0 -> -inf).
        float bx = F_INF, bm = 0.f, bb = 0.f;
#pragma unroll
        for (int k = 0; k < 8; k++) {
            float dj = m[k] - mc;
            float nj = bc - b[k];
            bool valid = (dj > 0.f) || (dj == 0.f && nj < 0.f);
            float x = valid ? __fdividef(nj, dj) : F_INF;
            if (x < bx) { bx = x; bm = m[k]; bb = b[k]; }
        }
        unsigned wk = __reduce_min_sync(0xFFFFFFFFu, fkey(bx));
        if (wk >= KEY_INF) break;                     // envelope complete
        unsigned bal = __ballot_sync(0xFFFFFFFFu, fkey(bx) == wk);
        int src = __ffs(bal) - 1;
        mc = __shfl_sync(0xFFFFFFFFu, bm, src);
        bc = __shfl_sync(0xFFFFFFFFu, bb, src);
    }

    for (int k = cnt + lane; k < HP; k += 32)
        store_line(hps, k, 0.f, F_NINF);
    if (lane == 0) g_cnt[branch][d][w] = cnt;
}

// ───────────────────────── eval kernel ─────────────────────────
// 128 CTAs: bid = branch (bx>>6) x batch-group of 16 (bx&63). 1024 threads
// = 32 warps (8/SMSP) for issue-efficiency. warp = (quad = warp&3 -> 4 q's,
// wblk = warp>>2 in 0..7); lane owns exactly ONE w = wblk*32+lane.
// Smem layout (stager == reader): granule g of w at buf + w*128 + ((g^(w&7))<<4).
// Triple-buffered cp.async (prefetch depth 2), ONE __syncthreads per layer.
#define BUFS       32768
#define EVAL_SMEM  (3 * BUFS + 512)

__global__ void __launch_bounds__(1024, 1) eval_kernel(
    const float* __restrict__ val, float* __restrict__ out) {
    extern __shared__ char smem[];
    float4* s_red = (float4*)(smem + 3 * BUFS);     // [8 wblk][4 quad]

    unsigned sbase;
    asm("{.reg .u64 t; cvta.to.shared.u64 t, %1; cvt.u32.u64 %0, t;}"
        : "=r"(sbase) : "l"(smem));

    const int t      = threadIdx.x;
    const int branch = blockIdx.x >> 6;
    const int grp    = blockIdx.x & 63;
    const int warp   = t >> 5;
    const int lane   = t & 31;
    const int quad   = warp & 3;
    const int wblk   = warp >> 2;
    const int w      = wblk * 32 + lane;            // this thread's w, all layers
    const int ws7    = w & 7;

    float q[4];
#pragma unroll
    for (int i = 0; i < 4; i++) q[i] = val[grp * 16 + quad * 4 + i];

    // Pre-stage layers 0 and 1: 2048 float4 per layer, 2 per thread.
#pragma unroll
    for (int L = 0; L < 2; L++) {
        const float4* src = &g_hullp[branch][L][0][0];
#pragma unroll
        for (int k = 0; k < 2; k++) {
            int n = t + (k << 10);                // 0..2047
            int ww = n >> 3, g = n & 7;
            unsigned dst = sbase + (unsigned)(L * BUFS + ww * 128 + ((g ^ (ww & 7)) << 4));
            CP_ASYNC16(dst, src + n);
        }
        CP_COMMIT();
    }

    for (int d = 0; d < DEPTH; ++d) {
        if (d < DEPTH - 1) CP_WAIT(1); else CP_WAIT(0);
        __syncthreads();   // layer-d staged; s_red[d-1] visible; buf (d+2)%3 free

        if (d > 0) {       // rebuild q: min over the 8 wblk partials (broadcast)
            float4 r = s_red[0 * 4 + quad];
            q[0] = r.x; q[1] = r.y; q[2] = r.z; q[3] = r.w;
#pragma unroll
            for (int wb = 1; wb < 8; wb++) {
                float4 s = s_red[wb * 4 + quad];
                q[0] = fminf(q[0], s.x);
                q[1] = fminf(q[1], s.y);
                q[2] = fminf(q[2], s.z);
                q[3] = fminf(q[3], s.w);
            }
        }
        uint64_t q2[4];
#pragma unroll
        for (int i = 0; i < 4; i++) q2[i] = pack_dup(q[i]);

        if (d + 2 < DEPTH) {                      // prefetch layer d+2
            const float4* src = &g_hullp[branch][d + 2][0][0];
            unsigned bufo = (unsigned)(((d + 2) % 3) * BUFS);
#pragma unroll
            for (int k = 0; k < 2; k++) {
                int n = t + (k << 10);
                int ww = n >> 3, g = n & 7;
                unsigned dst = sbase + bufo + (unsigned)(ww * 128 + ((g ^ (ww & 7)) << 4));
                CP_ASYNC16(dst, src + n);
            }
            CP_COMMIT();
        }

        const char* hw = smem + (d % 3) * BUFS + w * 128;

        float vmax[4] = {F_NINF, F_NINF, F_NINF, F_NINF};
        // Two register batches of 4 granules each (MLP=4, ~8 fewer live regs).
#pragma unroll
        for (int half = 0; half < 2; half++) {
            ulonglong2 P[4];
#pragma unroll
            for (int g = 0; g < 4; g++)
                P[g] = *(const ulonglong2*)(hw + (((half * 4 + g) ^ ws7) << 4));
#pragma unroll
            for (int g = 0; g < 4; g++) {
#pragma unroll
                for (int i = 0; i < 4; i++) {
                    uint64_t s;
                    ffma2(s, q2[i], P[g].x, P[g].y);
                    float lo, hi;
                    unpack2(lo, hi, s);
                    vmax[i] = fmaxf(vmax[i], lo);
                    vmax[i] = fmaxf(vmax[i], hi);
                }
            }
        }

        // Oversized hulls: warp-uniform gate; tail folds into vmax BEFORE min.
        int cw = g_cnt[branch][d][w];
        if (__reduce_max_sync(0xFFFFFFFFu, (unsigned)cw) > HP) {
            if (cw > HP) {
                const float2* fp = &g_hull[branch][d][w][0];
                for (int k = HP; k < cw; k++) {
                    float2 l2 = __ldg(fp + k);
#pragma unroll
                    for (int i = 0; i < 4; i++)
                        vmax[i] = fmaxf(vmax[i], fmaf(q[i], l2.x, l2.y));
                }
            }
        }

        // Warp-wide min over this warp's 32 w's: REDUX on ordered keys.
#pragma unroll
        for (int i = 0; i < 4; i++)
            vmax[i] = funkey(__reduce_min_sync(0xFFFFFFFFu, fkey(vmax[i])));
        if (lane == 0)
            s_red[wblk * 4 + quad] = make_float4(vmax[0], vmax[1], vmax[2], vmax[3]);
        // Published by next layer's barrier.
    }

    __syncthreads();
    if (t < 16) {
        const int qq = t >> 2, ii = t & 3;
        float acc = F_INF;
#pragma unroll
        for (int wb = 0; wb < 8; wb++) {
            float4 r = s_red[wb * 4 + qq];
            float v = (ii == 0) ? r.x : (ii == 1) ? r.y : (ii == 2) ? r.z : r.w;
            acc = fminf(acc, v);
        }
        out[branch * BATCH + grp * 16 + t] = acc;
    }
}

extern "C" void kernel_launch(void* const* d_in, const int* in_sizes, int n_in,
                              void* d_out, int out_size) {
    const float* val = (const float*)d_in[0];
    const float* M1  = (const float*)d_in[1];
    const float* B1  = (const float*)d_in[2];
    const float* M2  = (const float*)d_in[3];
    const float* B2  = (const float*)d_in[4];
    float* out = (float*)d_out;

    cudaFuncSetAttribute(eval_kernel,
                         cudaFuncAttributeMaxDynamicSharedMemorySize, EVAL_SMEM);

    hull_kernel<<<(2 * DEPTH * WDIM) / 8, 256>>>(M1, B1, M2, B2);
    eval_kernel<<<128, 1024, EVAL_SMEM>>>(val, out);
}

// round 11
// speedup vs baseline: 1.0918x; 1.0918x over previous
#include <cuda_runtime.h>
#include <cstdint>

#define BATCH   1024
#define WDIM    256
#define HDIM    256
#define DEPTH   8
#define HMAX    256     // absolute worst-case hull size
#define HP      12      // padded fast-path hull size (E[hull] ~ 6; P(>12) tiny)
#define NGRAN   (HP/2)  // 6 granules of 16B per w

#define F_INF   __int_as_float(0x7F800000)
#define F_NINF  __int_as_float(0xFF800000)

// Static device scratch (allocation-free rule).
// Padded hulls: per (branch,d,w) NGRAN granules of 16B; granule g holds lines
// 2g,2g+1 as (m0, m1, b0, b1) -> LDS.128 yields (m0,m1),(b0,b1) b64 pairs.
__device__ float2 g_hull [2][DEPTH][WDIM][HMAX];   // oversized tail (k >= HP only)
__device__ float4 g_hullp[2][DEPTH][WDIM][NGRAN];  // 6 granules = 96B per w
__device__ int    g_cnt  [2][DEPTH][WDIM];

// Monotone float <-> uint key (uint order == float order, incl. +-inf).
__device__ __forceinline__ unsigned fkey(float f) {
    unsigned u = __float_as_uint(f);
    return (u & 0x80000000u) ? ~u : (u | 0x80000000u);
}
__device__ __forceinline__ float funkey(unsigned k) {
    unsigned u = (k & 0x80000000u) ? (k & 0x7FFFFFFFu) : ~k;
    return __uint_as_float(u);
}

#define CP_ASYNC16(dst, src) \
    asm volatile("cp.async.cg.shared.global [%0], [%1], 16;" :: "r"(dst), "l"(src))
#define CP_COMMIT() asm volatile("cp.async.commit_group;")
#define CP_WAIT(n)  asm volatile("cp.async.wait_group %0;" :: "n"(n))

// Packed f32x2 helpers (FFMA2 in SASS).
__device__ __forceinline__ uint64_t pack_dup(float f) {
    uint64_t r;
    asm("mov.b64 %0, {%1, %1};" : "=l"(r) : "f"(f));
    return r;
}
__device__ __forceinline__ void ffma2(uint64_t& d, uint64_t a, uint64_t b, uint64_t c) {
    asm("fma.rn.f32x2 %0, %1, %2, %3;" : "=l"(d) : "l"(a), "l"(b), "l"(c));
}
__device__ __forceinline__ void unpack2(float& lo, float& hi, uint64_t v) {
    asm("mov.b64 {%0, %1}, %2;" : "=f"(lo), "=f"(hi) : "l"(v));
}

// Write line k (k < HP) of a padded hull in granule layout (m0,m1,b0,b1).
__device__ __forceinline__ void store_line(float* hps, int k, float m, float b) {
    int g = k >> 1, o = k & 1;
    hps[g * 4 + o]     = m;
    hps[g * 4 + 2 + o] = b;
}

// ───────────────────────── hull kernel ─────────────────────────
// One warp per envelope (branch, d, w): gift-wrap the upper envelope of the
// 256 lines y = m*q + b. 8 independent fdividefs per lane-step, REDUX argmin.
__global__ void __launch_bounds__(256) hull_kernel(
    const float* __restrict__ M1, const float* __restrict__ B1,
    const float* __restrict__ M2, const float* __restrict__ B2) {
    const int gw     = (blockIdx.x * blockDim.x + threadIdx.x) >> 5;  // 0..4095
    const int lane   = threadIdx.x & 31;
    const int branch = gw >> 11;
    const int d      = (gw >> 8) & 7;
    const int w      = gw & 255;

    const float* Mp = (branch ? M2 : M1) + (size_t)((d << 8) + w) * HDIM;
    const float* Bp = (branch ? B2 : B1) + (size_t)((d << 8) + w) * HDIM;

    float m[8], b[8];
    {
        const float4* M4 = (const float4*)Mp;
        const float4* B4 = (const float4*)Bp;
        float4 a0 = M4[lane * 2], a1 = M4[lane * 2 + 1];
        float4 c0 = B4[lane * 2], c1 = B4[lane * 2 + 1];
        m[0]=a0.x; m[1]=a0.y; m[2]=a0.z; m[3]=a0.w;
        m[4]=a1.x; m[5]=a1.y; m[6]=a1.z; m[7]=a1.w;
        b[0]=c0.x; b[1]=c0.y; b[2]=c0.z; b[3]=c0.w;
        b[4]=c1.x; b[5]=c1.y; b[6]=c1.z; b[7]=c1.w;
    }

    // Start line: min slope (dominated equal-slope start self-corrects).
    float mc = m[0], bc = b[0];
#pragma unroll
    for (int k = 1; k < 8; k++)
        if (m[k] < mc || (m[k] == mc && b[k] > bc)) { mc = m[k]; bc = b[k]; }
    {
        unsigned mk  = __reduce_min_sync(0xFFFFFFFFu, fkey(mc));
        unsigned bal = __ballot_sync(0xFFFFFFFFu, fkey(mc) == mk);
        int src = __ffs(bal) - 1;
        mc = __shfl_sync(0xFFFFFFFFu, mc, src);
        bc = __shfl_sync(0xFFFFFFFFu, bc, src);
    }

    float2* hf  = &g_hull[branch][d][w][0];
    float*  hps = (float*)&g_hullp[branch][d][w][0];
    const unsigned KEY_INF = fkey(F_INF);

    int cnt = 0;
    for (int step = 0; step < HMAX; ++step) {
        if (lane == 0) {
            if (cnt < HP) store_line(hps, cnt, mc, bc);
            else          hf[cnt] = make_float2(mc, bc);
        }
        cnt++;

        // Per-lane: smallest crossing x among overtaking lines.
        // dj==0 && nj<0 encodes x = -inf via fdividef (-/0 -> -inf).
        float bx = F_INF, bm = 0.f, bb = 0.f;
#pragma unroll
        for (int k = 0; k < 8; k++) {
            float dj = m[k] - mc;
            float nj = bc - b[k];
            bool valid = (dj > 0.f) || (dj == 0.f && nj < 0.f);
            float x = valid ? __fdividef(nj, dj) : F_INF;
            if (x < bx) { bx = x; bm = m[k]; bb = b[k]; }
        }
        unsigned wk = __reduce_min_sync(0xFFFFFFFFu, fkey(bx));
        if (wk >= KEY_INF) break;                     // envelope complete
        unsigned bal = __ballot_sync(0xFFFFFFFFu, fkey(bx) == wk);
        int src = __ffs(bal) - 1;
        mc = __shfl_sync(0xFFFFFFFFu, bm, src);
        bc = __shfl_sync(0xFFFFFFFFu, bb, src);
    }

    // Pad the compact hull with (0, -inf): neutral for max.
    for (int k = cnt + lane; k < HP; k += 32)
        store_line(hps, k, 0.f, F_NINF);
    if (lane == 0) g_cnt[branch][d][w] = cnt;
}

// ───────────────────────── eval kernel ─────────────────────────
// 128 CTAs: bid = branch (bx>>6) x batch-group of 16 (bx&63). 512 threads.
// Warp = (quad = warp&3 -> 4 q's, wblk = warp>>2); lane -> w0 = wblk*64+lane.
// Smem layout (stager == reader): granule g (0..5) of w at
//   buf + w*128 + ((g ^ (w&7)) << 4)        [128B stride, 96B used]
// -> across 8 consecutive lanes g^(w&7) permutes within 0..7: conflict-free.
// Triple-buffered cp.async (prefetch depth 2), ONE __syncthreads per layer.
#define BUFS       32768
#define EVAL_SMEM  (3 * BUFS + 256)
#define G4PL       (WDIM * NGRAN)     // float4s per layer = 1536

__global__ void __launch_bounds__(512, 1) eval_kernel(
    const float* __restrict__ val, float* __restrict__ out) {
    extern __shared__ char smem[];
    float4* s_red = (float4*)(smem + 3 * BUFS);     // [16 warps]

    unsigned sbase;
    asm("{.reg .u64 t; cvta.to.shared.u64 t, %1; cvt.u32.u64 %0, t;}"
        : "=r"(sbase) : "l"(smem));

    const int t      = threadIdx.x;
    const int branch = blockIdx.x >> 6;
    const int grp    = blockIdx.x & 63;
    const int warp   = t >> 5;
    const int lane   = t & 31;
    const int quad   = warp & 3;
    const int wblk   = warp >> 2;

    float q[4];
#pragma unroll
    for (int i = 0; i < 4; i++) q[i] = val[grp * 16 + quad * 4 + i];

    // Pre-stage layers 0 and 1: 1536 float4 per layer, 3 per thread.
#pragma unroll
    for (int L = 0; L < 2; L++) {
        const float4* src = &g_hullp[branch][L][0][0];
#pragma unroll
        for (int k = 0; k < 3; k++) {
            int n = t + (k << 9);                 // 0..1535
            int w = n / NGRAN, g = n % NGRAN;
            unsigned dst = sbase + (unsigned)(L * BUFS + w * 128 + ((g ^ (w & 7)) << 4));
            CP_ASYNC16(dst, src + n);
        }
        CP_COMMIT();
    }

    for (int d = 0; d < DEPTH; ++d) {
        if (d < DEPTH - 1) CP_WAIT(1); else CP_WAIT(0);
        __syncthreads();   // layer-d staged; s_red[d-1] visible; buf (d+2)%3 free

        if (d > 0) {       // rebuild q from the 4 wblk partials (broadcast LDS)
            float4 r0 = s_red[0 * 4 + quad];
            float4 r1 = s_red[1 * 4 + quad];
            float4 r2 = s_red[2 * 4 + quad];
            float4 r3 = s_red[3 * 4 + quad];
            q[0] = fminf(fminf(r0.x, r1.x), fminf(r2.x, r3.x));
            q[1] = fminf(fminf(r0.y, r1.y), fminf(r2.y, r3.y));
            q[2] = fminf(fminf(r0.z, r1.z), fminf(r2.z, r3.z));
            q[3] = fminf(fminf(r0.w, r1.w), fminf(r2.w, r3.w));
        }
        uint64_t q2[4];
#pragma unroll
        for (int i = 0; i < 4; i++) q2[i] = pack_dup(q[i]);

        if (d + 2 < DEPTH) {                      // prefetch layer d+2
            const float4* src = &g_hullp[branch][d + 2][0][0];
            unsigned bufo = (unsigned)(((d + 2) % 3) * BUFS);
#pragma unroll
            for (int k = 0; k < 3; k++) {
                int n = t + (k << 9);
                int w = n / NGRAN, g = n % NGRAN;
                unsigned dst = sbase + bufo + (unsigned)(w * 128 + ((g ^ (w & 7)) << 4));
                CP_ASYNC16(dst, src + n);
            }
            CP_COMMIT();
        }

        const char* hb = smem + (d % 3) * BUFS;
        const int w0 = wblk * 64 + lane;
        int cw0 = g_cnt[branch][d][w0];
        int cw1 = g_cnt[branch][d][w0 + 32];

        float vmin[4] = {F_INF, F_INF, F_INF, F_INF};
#pragma unroll
        for (int wo = 0; wo < 2; wo++) {
            const int w  = w0 + wo * 32;
            const int cw = wo ? cw1 : cw0;
            const char* hw = hb + w * 128;
            const int ws7 = w & 7;

            // Batch all 6 granules into registers first (MLP=6).
            ulonglong2 P[NGRAN];
#pragma unroll
            for (int g = 0; g < NGRAN; g++)
                P[g] = *(const ulonglong2*)(hw + ((g ^ ws7) << 4));

            float vmax[4] = {F_NINF, F_NINF, F_NINF, F_NINF};
#pragma unroll
            for (int g = 0; g < NGRAN; g++) {
#pragma unroll
                for (int i = 0; i < 4; i++) {
                    uint64_t s;
                    ffma2(s, q2[i], P[g].x, P[g].y);   // lines 2g, 2g+1 at q[i]
                    float lo, hi;
                    unpack2(lo, hi, s);
                    vmax[i] = fmaxf(vmax[i], lo);
                    vmax[i] = fmaxf(vmax[i], hi);
                }
            }

            // Oversized hulls: warp-uniform gate; tail folds into vmax BEFORE min.
            if (__reduce_max_sync(0xFFFFFFFFu, (unsigned)cw) > HP) {
                if (cw > HP) {
                    const float2* fp = &g_hull[branch][d][w][0];
                    for (int k = HP; k < cw; k++) {
                        float2 l2 = __ldg(fp + k);
#pragma unroll
                        for (int i = 0; i < 4; i++)
                            vmax[i] = fmaxf(vmax[i], fmaf(q[i], l2.x, l2.y));
                    }
                }
            }
#pragma unroll
            for (int i = 0; i < 4; i++) vmin[i] = fminf(vmin[i], vmax[i]);
        }

        // Warp-wide min over this warp's 64 w's: REDUX on ordered keys.
#pragma unroll
        for (int i = 0; i < 4; i++)
            vmin[i] = funkey(__reduce_min_sync(0xFFFFFFFFu, fkey(vmin[i])));
        if (lane == 0)
            s_red[warp] = make_float4(vmin[0], vmin[1], vmin[2], vmin[3]);
        // Published by next layer's barrier.
    }

    __syncthreads();
    if (t < 16) {
        const int qq = t >> 2, ii = t & 3;
        float acc = F_INF;
#pragma unroll
        for (int wb = 0; wb < 4; wb++) {
            float4 r = s_red[wb * 4 + qq];
            float v = (ii == 0) ? r.x : (ii == 1) ? r.y : (ii == 2) ? r.z : r.w;
            acc = fminf(acc, v);
        }
        out[branch * BATCH + grp * 16 + t] = acc;
    }
}

extern "C" void kernel_launch(void* const* d_in, const int* in_sizes, int n_in,
                              void* d_out, int out_size) {
    const float* val = (const float*)d_in[0];
    const float* M1  = (const float*)d_in[1];
    const float* B1  = (const float*)d_in[2];
    const float* M2  = (const float*)d_in[3];
    const float* B2  = (const float*)d_in[4];
    float* out = (float*)d_out;

    cudaFuncSetAttribute(eval_kernel,
                         cudaFuncAttributeMaxDynamicSharedMemorySize, EVAL_SMEM);

    hull_kernel<<<(2 * DEPTH * WDIM) / 8, 256>>>(M1, B1, M2, B2);
    eval_kernel<<<128, 512, EVAL_SMEM>>>(val, out);
}